// round 2
// baseline (speedup 1.0000x reference)
#include <cuda_runtime.h>
#include <cuda_fp16.h>
#include <cstdint>

#define NTOK   49
#define NHD    8
#define HDIM   32
#define DMODEL 256
#define NBATCH 4096
#define NWIN   64
#define MROWS  (NBATCH * NTOK)   // 200704

// fp16 scratch (no allocation allowed): Q/K/V in [B][NH][49][32], X fp16, W^T fp16.
__device__ __half g_q[(size_t)NBATCH * NHD * NTOK * HDIM];
__device__ __half g_k[(size_t)NBATCH * NHD * NTOK * HDIM];
__device__ __half g_v[(size_t)NBATCH * NHD * NTOK * HDIM];
__device__ __half g_x[(size_t)MROWS * DMODEL];
__device__ __half g_w[3 * 256 * 256];   // [mat][n][k]  (W transposed)

__device__ __forceinline__ void mma16816(float c[4],
                                         uint32_t a0, uint32_t a1, uint32_t a2, uint32_t a3,
                                         uint32_t b0, uint32_t b1) {
    asm volatile(
        "mma.sync.aligned.m16n8k16.row.col.f32.f16.f16.f32 "
        "{%0,%1,%2,%3}, {%4,%5,%6,%7}, {%8,%9}, {%0,%1,%2,%3};"
        : "+f"(c[0]), "+f"(c[1]), "+f"(c[2]), "+f"(c[3])
        : "r"(a0), "r"(a1), "r"(a2), "r"(a3), "r"(b0), "r"(b1));
}

__device__ __forceinline__ void ldsm4(uint32_t r[4], const void* p) {
    uint32_t a = (uint32_t)__cvta_generic_to_shared(p);
    asm volatile("ldmatrix.sync.aligned.m8n8.x4.shared.b16 {%0,%1,%2,%3}, [%4];"
                 : "=r"(r[0]), "=r"(r[1]), "=r"(r[2]), "=r"(r[3]) : "r"(a));
}

__device__ __forceinline__ void cp16(void* s, const void* g) {
    uint32_t sa = (uint32_t)__cvta_generic_to_shared(s);
    asm volatile("cp.async.cg.shared.global [%0], [%1], 16;" :: "r"(sa), "l"(g));
}

// ---------------------------------------------------------------------------
// Pre-convert X (fp32 -> fp16). 51,380,224 elems = 50176 blocks * 256 thr * 4.
// ---------------------------------------------------------------------------
__global__ __launch_bounds__(256) void convert_x(const float* __restrict__ X) {
    size_t t = (size_t)blockIdx.x * 256 + threadIdx.x;
    float4 v = ((const float4*)X)[t];
    __half2* o = (__half2*)(g_x + t * 4);
    o[0] = __floats2half2_rn(v.x, v.y);
    o[1] = __floats2half2_rn(v.z, v.w);
}

// Pre-convert + transpose weights: g_w[mat][n][k] = W[k][n]. grid (3, 256) x 256.
__global__ __launch_bounds__(256) void convert_w(const float* __restrict__ wq,
                                                 const float* __restrict__ wk,
                                                 const float* __restrict__ wv) {
    int mat = blockIdx.x, k = blockIdx.y, n = threadIdx.x;
    const float* W = (mat == 0) ? wq : (mat == 1) ? wk : wv;
    g_w[((size_t)mat * 256 + n) * 256 + k] = __float2half_rn(W[k * 256 + n]);
}

// ---------------------------------------------------------------------------
// Kernel A: QKV projection, fp16 in/out, fp32 accum.
// BM=128, BN=128, full K=256 resident in smem (135KB dyn). 256 thr = 8 warps
// (2m x 4n), warp tile 64x32. cp.async in 2 K-halves (pipelined), ldmatrix
// fragment loads, zero inner syncs. grid (6, 1568), x fastest for A reuse.
// ---------------------------------------------------------------------------
__global__ __launch_bounds__(256) void qkv_kernel(
    const float* __restrict__ bq, const float* __restrict__ bk,
    const float* __restrict__ bv)
{
    extern __shared__ char dsm[];
    __half (*As)[264] = (__half(*)[264])dsm;
    __half (*Bs)[264] = (__half(*)[264])(dsm + 128 * 264 * 2);

    const int bx = blockIdx.x, by = blockIdx.y;
    const int tid = threadIdx.x;
    const int warp = tid >> 5, lane = tid & 31;
    const int wm = warp & 1, wn = warp >> 1;
    const int g = lane >> 2, tig = lane & 3;

    const int mat   = bx >> 1;             // 0=Q 1=K 2=V
    const int ncol0 = (bx & 1) * 128;
    const float* bias = (mat == 0) ? bq : (mat == 1) ? bk : bv;

    const __half* xrow  = g_x + (size_t)by * 128 * 256;
    const __half* wbase = g_w + ((size_t)mat * 256 + ncol0) * 256;

    // Two cp.async groups: K cols [0,128) then [128,256).
#pragma unroll
    for (int hk = 0; hk < 2; hk++) {
        for (int c = tid; c < 2048; c += 256) {
            int r = c >> 4, off = hk * 128 + (c & 15) * 8;
            cp16(&As[r][off], xrow + (size_t)r * 256 + off);
        }
        for (int c = tid; c < 2048; c += 256) {
            int n = c >> 4, off = hk * 128 + (c & 15) * 8;
            cp16(&Bs[n][off], wbase + (size_t)n * 256 + off);
        }
        asm volatile("cp.async.commit_group;" ::: "memory");
    }

    float acc[4][4][4];
#pragma unroll
    for (int mt = 0; mt < 4; mt++)
#pragma unroll
        for (int nt = 0; nt < 4; nt++)
#pragma unroll
            for (int e = 0; e < 4; e++) acc[mt][nt][e] = 0.f;

    // ldmatrix per-lane addressing
    const int aRow = wm * 64 + (lane & 15);
    const int aCol = (lane & 16) >> 1;                        // 0 or 8
    const int bRow = wn * 32 + (lane & 7) + ((lane & 16) >> 1);
    const int bCol = lane & 8;                                 // 0 or 8

    asm volatile("cp.async.wait_group 1;" ::: "memory");
    __syncthreads();

#pragma unroll
    for (int ks = 0; ks < 8; ks++) {
        const int kc = ks * 16;
        uint32_t bf0[4], bf1[4];
        ldsm4(bf0, &Bs[bRow][kc + bCol]);
        ldsm4(bf1, &Bs[bRow + 16][kc + bCol]);
#pragma unroll
        for (int mt = 0; mt < 4; mt++) {
            uint32_t a[4];
            ldsm4(a, &As[aRow + mt * 16][kc + aCol]);
            mma16816(acc[mt][0], a[0], a[1], a[2], a[3], bf0[0], bf0[1]);
            mma16816(acc[mt][1], a[0], a[1], a[2], a[3], bf0[2], bf0[3]);
            mma16816(acc[mt][2], a[0], a[1], a[2], a[3], bf1[0], bf1[1]);
            mma16816(acc[mt][3], a[0], a[1], a[2], a[3], bf1[2], bf1[3]);
        }
    }

    asm volatile("cp.async.wait_group 0;" ::: "memory");
    __syncthreads();

#pragma unroll
    for (int ks = 8; ks < 16; ks++) {
        const int kc = ks * 16;
        uint32_t bf0[4], bf1[4];
        ldsm4(bf0, &Bs[bRow][kc + bCol]);
        ldsm4(bf1, &Bs[bRow + 16][kc + bCol]);
#pragma unroll
        for (int mt = 0; mt < 4; mt++) {
            uint32_t a[4];
            ldsm4(a, &As[aRow + mt * 16][kc + aCol]);
            mma16816(acc[mt][0], a[0], a[1], a[2], a[3], bf0[0], bf0[1]);
            mma16816(acc[mt][1], a[0], a[1], a[2], a[3], bf0[2], bf0[3]);
            mma16816(acc[mt][2], a[0], a[1], a[2], a[3], bf1[0], bf1[1]);
            mma16816(acc[mt][3], a[0], a[1], a[2], a[3], bf1[2], bf1[3]);
        }
    }

    // Epilogue: bias add, Q scale, scatter as half2 into [B][NH][49][32].
    __half* outp = (mat == 0) ? g_q : (mat == 1) ? g_k : g_v;
    const float scale = (mat == 0) ? 0.17677669529663687f : 1.0f;
#pragma unroll
    for (int mt = 0; mt < 4; mt++) {
#pragma unroll
        for (int hf = 0; hf < 2; hf++) {
            int m = by * 128 + wm * 64 + mt * 16 + g + hf * 8;
            int b = m / NTOK, n = m - b * NTOK;
#pragma unroll
            for (int nt = 0; nt < 4; nt++) {
                int c = ncol0 + wn * 32 + nt * 8 + 2 * tig;
                int h = c >> 5, d = c & 31;
                float v0 = (acc[mt][nt][hf * 2 + 0] + bias[c]) * scale;
                float v1 = (acc[mt][nt][hf * 2 + 1] + bias[c + 1]) * scale;
                *(__half2*)(outp + ((((size_t)b * NHD + h) * NTOK + n) * HDIM + d)) =
                    __floats2half2_rn(v0, v1);
            }
        }
    }
}

// ---------------------------------------------------------------------------
// Kernel B: windowed attention. CTA = (window b, half of heads): 128 thr,
// warp w owns head h = blockIdx.y*4 + w completely (4 m16 row tiles).
// Mask + bias table in smem shared by the 4 heads. Warp-private Q/K/V/P smem.
// ---------------------------------------------------------------------------
__device__ __forceinline__ int relidx(int i, int j) {
    int ih = i / 7, iw = i - ih * 7;
    int jh = j / 7, jw = j - jh * 7;
    return (ih - jh + 6) * 13 + (iw - jw + 6);
}

#define HEAD_OFF   15232
#define HEAD_SZ    16000
#define ATTN_SMEM  (HEAD_OFF + 4 * HEAD_SZ)   // 79232

__global__ __launch_bounds__(128) void attn_kernel(
    const float* __restrict__ mask,     // [64,49,49]
    const float* __restrict__ table,    // [169,8]
    float* __restrict__ out)            // [4096,49,256]
{
    extern __shared__ char dsm[];
    float* s_mask = (float*)dsm;                 // 2401 floats
    float* s_tab  = (float*)(dsm + 9728);        // 1352 floats

    const int b = blockIdx.x;
    const int w = b & (NWIN - 1);
    const int tid = threadIdx.x, warp = tid >> 5, lane = tid & 31;
    const int h = blockIdx.y * 4 + warp;
    const int g = lane >> 2, tig = lane & 3;

    char* hb = dsm + HEAD_OFF + warp * HEAD_SZ;
    __half (*Qs)[40] = (__half(*)[40])hb;                 // 64 x 40
    __half (*Ks)[40] = (__half(*)[40])(hb + 5120);        // 56 x 40
    __half (*Vt)[66] = (__half(*)[66])(hb + 9600);        // 32 x 66  (Vt[d][j])
    __half (*Ps)[66] = (__half(*)[66])(hb + 13824);       // 16 x 66

    // CTA-wide: mask + table into smem
    for (int i = tid; i < NTOK * NTOK; i += 128) s_mask[i] = mask[w * NTOK * NTOK + i];
    for (int i = tid; i < 169 * NHD;   i += 128) s_tab[i]  = table[i];

    // Warp-private loads of this head's Q, K, V
    const size_t base = ((size_t)b * NHD + h) * (NTOK * HDIM);
    const __half2* qp2 = (const __half2*)(g_q + base);
    const __half2* kp2 = (const __half2*)(g_k + base);
    const __half*  vp  = g_v + base;
    const __half2 z2 = __float2half2_rn(0.f);

    for (int i = lane; i < 64 * 16; i += 32) {
        int r = i >> 4, c = i & 15;
        *(__half2*)&Qs[r][c * 2] = (r < NTOK) ? qp2[r * 16 + c] : z2;
    }
    for (int i = lane; i < 56 * 16; i += 32) {
        int r = i >> 4, c = i & 15;
        *(__half2*)&Ks[r][c * 2] = (r < NTOK) ? kp2[r * 16 + c] : z2;
    }
    // Vt pad cols [49,66) zero, then fill j<49
    for (int i = lane; i < 32 * 17; i += 32) {
        int d = i / 17, j = 49 + (i % 17);
        Vt[d][j] = __float2half(0.f);
    }
    for (int i = lane; i < NTOK * HDIM; i += 32) {
        int j = i >> 5, d = i & 31;
        Vt[d][j] = vp[i];
    }
    // Ps pad cols [56,64) zero (cols <56 written every m-tile)
    for (int i = lane; i < 16 * 8; i += 32) {
        int r = i >> 3, c = 56 + (i & 7);
        Ps[r][c] = __float2half(0.f);
    }
    __syncthreads();

#pragma unroll
    for (int mt = 0; mt < 4; mt++) {
        const int i0 = mt * 16 + g, i1 = i0 + 8;

        // scores = Q @ K^T
        float sc[7][4];
#pragma unroll
        for (int nt = 0; nt < 7; nt++)
#pragma unroll
            for (int e = 0; e < 4; e++) sc[nt][e] = 0.f;

#pragma unroll
        for (int ks = 0; ks < 2; ks++) {
            uint32_t a0 = *(const uint32_t*)&Qs[i0][ks * 16 + 2 * tig];
            uint32_t a1 = *(const uint32_t*)&Qs[i1][ks * 16 + 2 * tig];
            uint32_t a2 = *(const uint32_t*)&Qs[i0][ks * 16 + 2 * tig + 8];
            uint32_t a3 = *(const uint32_t*)&Qs[i1][ks * 16 + 2 * tig + 8];
#pragma unroll
            for (int nt = 0; nt < 7; nt++) {
                int n = nt * 8 + g;
                uint32_t b0 = *(const uint32_t*)&Ks[n][ks * 16 + 2 * tig];
                uint32_t b1 = *(const uint32_t*)&Ks[n][ks * 16 + 2 * tig + 8];
                mma16816(sc[nt], a0, a1, a2, a3, b0, b1);
            }
        }

        // bias + mask + padding
#pragma unroll
        for (int nt = 0; nt < 7; nt++) {
#pragma unroll
            for (int e = 0; e < 4; e++) {
                int i = (e < 2) ? i0 : i1;
                int j = nt * 8 + 2 * tig + (e & 1);
                if (j < NTOK) {
                    if (i < NTOK)
                        sc[nt][e] += s_tab[relidx(i, j) * NHD + h] + s_mask[i * NTOK + j];
                } else {
                    sc[nt][e] = -1e30f;
                }
            }
        }

        // softmax (rows i0, i1; reduce across tig lanes)
        float mx0 = -1e30f, mx1 = -1e30f;
#pragma unroll
        for (int nt = 0; nt < 7; nt++) {
            mx0 = fmaxf(mx0, fmaxf(sc[nt][0], sc[nt][1]));
            mx1 = fmaxf(mx1, fmaxf(sc[nt][2], sc[nt][3]));
        }
        mx0 = fmaxf(mx0, __shfl_xor_sync(0xffffffffu, mx0, 1));
        mx0 = fmaxf(mx0, __shfl_xor_sync(0xffffffffu, mx0, 2));
        mx1 = fmaxf(mx1, __shfl_xor_sync(0xffffffffu, mx1, 1));
        mx1 = fmaxf(mx1, __shfl_xor_sync(0xffffffffu, mx1, 2));

        float s0 = 0.f, s1 = 0.f;
#pragma unroll
        for (int nt = 0; nt < 7; nt++) {
            sc[nt][0] = __expf(sc[nt][0] - mx0); s0 += sc[nt][0];
            sc[nt][1] = __expf(sc[nt][1] - mx0); s0 += sc[nt][1];
            sc[nt][2] = __expf(sc[nt][2] - mx1); s1 += sc[nt][2];
            sc[nt][3] = __expf(sc[nt][3] - mx1); s1 += sc[nt][3];
        }
        s0 += __shfl_xor_sync(0xffffffffu, s0, 1);
        s0 += __shfl_xor_sync(0xffffffffu, s0, 2);
        s1 += __shfl_xor_sync(0xffffffffu, s1, 1);
        s1 += __shfl_xor_sync(0xffffffffu, s1, 2);
        const float r0 = 1.f / s0, r1 = 1.f / s1;

        // stage P (rows g, g+8 of the 16-row tile)
#pragma unroll
        for (int nt = 0; nt < 7; nt++) {
            *(__half2*)&Ps[g][nt * 8 + 2 * tig]     = __floats2half2_rn(sc[nt][0], sc[nt][1]);
            *(__half2*)&Ps[g + 8][nt * 8 + 2 * tig] = __floats2half2_rn(sc[nt][2], sc[nt][3]);
        }
        __syncwarp();

        // ctx = P @ V
        float o[4][4];
#pragma unroll
        for (int nt = 0; nt < 4; nt++)
#pragma unroll
            for (int e = 0; e < 4; e++) o[nt][e] = 0.f;

#pragma unroll
        for (int kt = 0; kt < 4; kt++) {
            uint32_t a0 = *(const uint32_t*)&Ps[g][kt * 16 + 2 * tig];
            uint32_t a1 = *(const uint32_t*)&Ps[g + 8][kt * 16 + 2 * tig];
            uint32_t a2 = *(const uint32_t*)&Ps[g][kt * 16 + 2 * tig + 8];
            uint32_t a3 = *(const uint32_t*)&Ps[g + 8][kt * 16 + 2 * tig + 8];
#pragma unroll
            for (int nt = 0; nt < 4; nt++) {
                int n = nt * 8 + g;
                uint32_t b0 = *(const uint32_t*)&Vt[n][kt * 16 + 2 * tig];
                uint32_t b1 = *(const uint32_t*)&Vt[n][kt * 16 + 2 * tig + 8];
                mma16816(o[nt], a0, a1, a2, a3, b0, b1);
            }
        }
        __syncwarp();

        // write output
#pragma unroll
        for (int nt = 0; nt < 4; nt++) {
            int d = nt * 8 + 2 * tig;
            if (i0 < NTOK) {
                float2 v = make_float2(o[nt][0] * r0, o[nt][1] * r0);
                *(float2*)(out + ((size_t)b * NTOK + i0) * DMODEL + h * HDIM + d) = v;
            }
            if (i1 < NTOK) {
                float2 v = make_float2(o[nt][2] * r1, o[nt][3] * r1);
                *(float2*)(out + ((size_t)b * NTOK + i1) * DMODEL + h * HDIM + d) = v;
            }
        }
    }
}

extern "C" void kernel_launch(void* const* d_in, const int* in_sizes, int n_in,
                              void* d_out, int out_size)
{
    (void)in_sizes; (void)n_in; (void)out_size;
    const float* hidden = (const float*)d_in[0];
    const float* amask  = (const float*)d_in[1];
    const float* wq     = (const float*)d_in[2];
    const float* bq     = (const float*)d_in[3];
    const float* wk     = (const float*)d_in[4];
    const float* bk     = (const float*)d_in[5];
    const float* wv     = (const float*)d_in[6];
    const float* bv     = (const float*)d_in[7];
    const float* table  = (const float*)d_in[8];
    float* out = (float*)d_out;

    cudaFuncSetAttribute(qkv_kernel, cudaFuncAttributeMaxDynamicSharedMemorySize,
                         2 * 128 * 264 * 2);
    cudaFuncSetAttribute(attn_kernel, cudaFuncAttributeMaxDynamicSharedMemorySize,
                         ATTN_SMEM);

    convert_x<<<50176, 256>>>(hidden);
    convert_w<<<dim3(3, 256), 256>>>(wq, wk, wv);
    qkv_kernel<<<dim3(6, 1568), 256, 2 * 128 * 264 * 2>>>(bq, bk, bv);
    attn_kernel<<<dim3(NBATCH, 2), 128, ATTN_SMEM>>>(amask, table, out);
}

// round 3
// speedup vs baseline: 2.1951x; 2.1951x over previous
#include <cuda_runtime.h>
#include <cuda_fp16.h>
#include <cstdint>

#define NTOK   49
#define NHD    8
#define HDIM   32
#define DMODEL 256
#define NBATCH 4096
#define NWIN   64
#define MROWS  (NBATCH * NTOK)   // 200704

// fp16 scratch (no allocation allowed): Q/K/V in [B][NH][49][32], X fp16, W^T fp16.
__device__ __half g_q[(size_t)NBATCH * NHD * NTOK * HDIM];
__device__ __half g_k[(size_t)NBATCH * NHD * NTOK * HDIM];
__device__ __half g_v[(size_t)NBATCH * NHD * NTOK * HDIM];
__device__ __half g_x[(size_t)MROWS * DMODEL];
__device__ __half g_w[3 * 256 * 256];          // [mat][n][k]  (W transposed)
__device__ float  g_bm[NWIN * NHD * 64 * 56];  // combined mask+bias, padded

__device__ __forceinline__ void mma16816(float c[4],
                                         uint32_t a0, uint32_t a1, uint32_t a2, uint32_t a3,
                                         uint32_t b0, uint32_t b1) {
    asm volatile(
        "mma.sync.aligned.m16n8k16.row.col.f32.f16.f16.f32 "
        "{%0,%1,%2,%3}, {%4,%5,%6,%7}, {%8,%9}, {%0,%1,%2,%3};"
        : "+f"(c[0]), "+f"(c[1]), "+f"(c[2]), "+f"(c[3])
        : "r"(a0), "r"(a1), "r"(a2), "r"(a3), "r"(b0), "r"(b1));
}

__device__ __forceinline__ void ldsm4(uint32_t r[4], const void* p) {
    uint32_t a = (uint32_t)__cvta_generic_to_shared(p);
    asm volatile("ldmatrix.sync.aligned.m8n8.x4.shared.b16 {%0,%1,%2,%3}, [%4];"
                 : "=r"(r[0]), "=r"(r[1]), "=r"(r[2]), "=r"(r[3]) : "r"(a));
}

__device__ __forceinline__ void cp16(void* s, const void* g) {
    uint32_t sa = (uint32_t)__cvta_generic_to_shared(s);
    asm volatile("cp.async.cg.shared.global [%0], [%1], 16;" :: "r"(sa), "l"(g));
}

// ---------------------------------------------------------------------------
// Pre-convert X (fp32 -> fp16).
// ---------------------------------------------------------------------------
__global__ __launch_bounds__(256) void convert_x(const float* __restrict__ X) {
    size_t t = (size_t)blockIdx.x * 256 + threadIdx.x;
    float4 v = ((const float4*)X)[t];
    __half2* o = (__half2*)(g_x + t * 4);
    o[0] = __floats2half2_rn(v.x, v.y);
    o[1] = __floats2half2_rn(v.z, v.w);
}

// Pre-convert + transpose weights: g_w[mat][n][k] = W[k][n]. grid (3,256) x 256.
__global__ __launch_bounds__(256) void convert_w(const float* __restrict__ wq,
                                                 const float* __restrict__ wk,
                                                 const float* __restrict__ wv) {
    int mat = blockIdx.x, k = blockIdx.y, n = threadIdx.x;
    const float* W = (mat == 0) ? wq : (mat == 1) ? wk : wv;
    g_w[((size_t)mat * 256 + n) * 256 + k] = __float2half_rn(W[k * 256 + n]);
}

// ---------------------------------------------------------------------------
// Combined bias+mask: g_bm[w][h][i][j] (i<64, j<56).
//   j<49 && i<49 : mask[w][i][j] + table[relidx(i,j)][h]
//   j>=49        : -1e30   (key padding)
//   else         : 0       (query padding rows, values unused)
// grid (64, 8) x 256 threads.
// ---------------------------------------------------------------------------
__global__ __launch_bounds__(256) void combine_bm(const float* __restrict__ mask,
                                                  const float* __restrict__ table) {
    const int w = blockIdx.x, h = blockIdx.y;
    float* dst = g_bm + ((size_t)(w * NHD + h)) * 64 * 56;
    for (int idx = threadIdx.x; idx < 64 * 56; idx += 256) {
        int i = idx / 56, j = idx - i * 56;
        float v;
        if (j >= NTOK)      v = -1e30f;
        else if (i >= NTOK) v = 0.f;
        else {
            int ih = i / 7, iw = i - ih * 7;
            int jh = j / 7, jw = j - jh * 7;
            int r = (ih - jh + 6) * 13 + (iw - jw + 6);
            v = mask[((size_t)w * NTOK + i) * NTOK + j] + table[r * NHD + h];
        }
        dst[idx] = v;
    }
}

// ---------------------------------------------------------------------------
// Kernel A: QKV projection, fp16 in/out, fp32 accum. (unchanged from R2)
// BM=128, BN=128, full K=256 resident in smem. 256 thr = 8 warps (2m x 4n).
// ---------------------------------------------------------------------------
__global__ __launch_bounds__(256) void qkv_kernel(
    const float* __restrict__ bq, const float* __restrict__ bk,
    const float* __restrict__ bv)
{
    extern __shared__ char dsm[];
    __half (*As)[264] = (__half(*)[264])dsm;
    __half (*Bs)[264] = (__half(*)[264])(dsm + 128 * 264 * 2);

    const int bx = blockIdx.x, by = blockIdx.y;
    const int tid = threadIdx.x;
    const int warp = tid >> 5, lane = tid & 31;
    const int wm = warp & 1, wn = warp >> 1;
    const int g = lane >> 2, tig = lane & 3;

    const int mat   = bx >> 1;
    const int ncol0 = (bx & 1) * 128;
    const float* bias = (mat == 0) ? bq : (mat == 1) ? bk : bv;

    const __half* xrow  = g_x + (size_t)by * 128 * 256;
    const __half* wbase = g_w + ((size_t)mat * 256 + ncol0) * 256;

#pragma unroll
    for (int hk = 0; hk < 2; hk++) {
        for (int c = tid; c < 2048; c += 256) {
            int r = c >> 4, off = hk * 128 + (c & 15) * 8;
            cp16(&As[r][off], xrow + (size_t)r * 256 + off);
        }
        for (int c = tid; c < 2048; c += 256) {
            int n = c >> 4, off = hk * 128 + (c & 15) * 8;
            cp16(&Bs[n][off], wbase + (size_t)n * 256 + off);
        }
        asm volatile("cp.async.commit_group;" ::: "memory");
    }

    float acc[4][4][4];
#pragma unroll
    for (int mt = 0; mt < 4; mt++)
#pragma unroll
        for (int nt = 0; nt < 4; nt++)
#pragma unroll
            for (int e = 0; e < 4; e++) acc[mt][nt][e] = 0.f;

    const int aRow = wm * 64 + (lane & 15);
    const int aCol = (lane & 16) >> 1;
    const int bRow = wn * 32 + (lane & 7) + ((lane & 16) >> 1);
    const int bCol = lane & 8;

    asm volatile("cp.async.wait_group 1;" ::: "memory");
    __syncthreads();

#pragma unroll
    for (int ks = 0; ks < 8; ks++) {
        const int kc = ks * 16;
        uint32_t bf0[4], bf1[4];
        ldsm4(bf0, &Bs[bRow][kc + bCol]);
        ldsm4(bf1, &Bs[bRow + 16][kc + bCol]);
#pragma unroll
        for (int mt = 0; mt < 4; mt++) {
            uint32_t a[4];
            ldsm4(a, &As[aRow + mt * 16][kc + aCol]);
            mma16816(acc[mt][0], a[0], a[1], a[2], a[3], bf0[0], bf0[1]);
            mma16816(acc[mt][1], a[0], a[1], a[2], a[3], bf0[2], bf0[3]);
            mma16816(acc[mt][2], a[0], a[1], a[2], a[3], bf1[0], bf1[1]);
            mma16816(acc[mt][3], a[0], a[1], a[2], a[3], bf1[2], bf1[3]);
        }
    }

    asm volatile("cp.async.wait_group 0;" ::: "memory");
    __syncthreads();

#pragma unroll
    for (int ks = 8; ks < 16; ks++) {
        const int kc = ks * 16;
        uint32_t bf0[4], bf1[4];
        ldsm4(bf0, &Bs[bRow][kc + bCol]);
        ldsm4(bf1, &Bs[bRow + 16][kc + bCol]);
#pragma unroll
        for (int mt = 0; mt < 4; mt++) {
            uint32_t a[4];
            ldsm4(a, &As[aRow + mt * 16][kc + aCol]);
            mma16816(acc[mt][0], a[0], a[1], a[2], a[3], bf0[0], bf0[1]);
            mma16816(acc[mt][1], a[0], a[1], a[2], a[3], bf0[2], bf0[3]);
            mma16816(acc[mt][2], a[0], a[1], a[2], a[3], bf1[0], bf1[1]);
            mma16816(acc[mt][3], a[0], a[1], a[2], a[3], bf1[2], bf1[3]);
        }
    }

    __half* outp = (mat == 0) ? g_q : (mat == 1) ? g_k : g_v;
    const float scale = (mat == 0) ? 0.17677669529663687f : 1.0f;
#pragma unroll
    for (int mt = 0; mt < 4; mt++) {
#pragma unroll
        for (int hf = 0; hf < 2; hf++) {
            int m = by * 128 + wm * 64 + mt * 16 + g + hf * 8;
            int b = m / NTOK, n = m - b * NTOK;
#pragma unroll
            for (int nt = 0; nt < 4; nt++) {
                int c = ncol0 + wn * 32 + nt * 8 + 2 * tig;
                int h = c >> 5, d = c & 31;
                float v0 = (acc[mt][nt][hf * 2 + 0] + bias[c]) * scale;
                float v1 = (acc[mt][nt][hf * 2 + 1] + bias[c + 1]) * scale;
                *(__half2*)(outp + ((((size_t)b * NHD + h) * NTOK + n) * HDIM + d)) =
                    __floats2half2_rn(v0, v1);
            }
        }
    }
}

// ---------------------------------------------------------------------------
// Kernel B: windowed attention. Round-1 parallelism: one 128-thr CTA per
// (b, h), 4 warps = 4 m16 row tiles. Bias+mask from precomputed g_bm
// (no relidx, no branches, float2 loads).
// ---------------------------------------------------------------------------
__global__ __launch_bounds__(128) void attn_kernel(float* __restrict__ out)
{
    const int b = blockIdx.x;
    const int h = blockIdx.y;
    const int w = b & (NWIN - 1);

    __shared__ __half Qs[64][40];
    __shared__ __half Ks[56][40];
    __shared__ __half VsT[32][72];
    __shared__ __half Ps[64][72];

    const int tid = threadIdx.x;
    const int warp = tid >> 5, lane = tid & 31;
    const int g = lane >> 2, tig = lane & 3;

    const size_t base = ((size_t)b * NHD + h) * (NTOK * HDIM);
    const __half2* qp2 = (const __half2*)(g_q + base);
    const __half2* kp2 = (const __half2*)(g_k + base);
    const __half*  vp  = g_v + base;
    const float* bm = g_bm + ((size_t)(w * NHD + h)) * 64 * 56;

    const __half2 zero2 = __float2half2_rn(0.f);

    for (int idx = tid; idx < 64 * 16; idx += 128) {
        int r = idx >> 4, c2 = idx & 15;
        *(__half2*)&Qs[r][c2 * 2] = (r < NTOK) ? qp2[r * 16 + c2] : zero2;
    }
    for (int idx = tid; idx < 56 * 16; idx += 128) {
        int r = idx >> 4, c2 = idx & 15;
        *(__half2*)&Ks[r][c2 * 2] = (r < NTOK) ? kp2[r * 16 + c2] : zero2;
    }
    for (int idx = tid; idx < 32 * 16; idx += 128) {
        int d = idx >> 4, j = 48 + (idx & 15);
        VsT[d][j] = __float2half(0.f);
    }
    for (int idx = tid; idx < NTOK * HDIM; idx += 128) {
        int j = idx >> 5, d = idx & 31;
        VsT[d][j] = vp[idx];
    }
    for (int idx = tid; idx < 64 * 8; idx += 128) {
        int r = idx >> 3, c = 56 + (idx & 7);
        Ps[r][c] = __float2half(0.f);
    }
    __syncthreads();

    const int m0 = warp * 16;
    const int i0 = m0 + g, i1 = m0 + g + 8;

    // --- scores = Q @ K^T ---
    float sc[7][4];
#pragma unroll
    for (int nt = 0; nt < 7; nt++)
#pragma unroll
        for (int e = 0; e < 4; e++) sc[nt][e] = 0.f;

#pragma unroll
    for (int ks = 0; ks < 2; ks++) {
        uint32_t a0 = *(const uint32_t*)&Qs[i0][ks * 16 + 2 * tig];
        uint32_t a1 = *(const uint32_t*)&Qs[i1][ks * 16 + 2 * tig];
        uint32_t a2 = *(const uint32_t*)&Qs[i0][ks * 16 + 2 * tig + 8];
        uint32_t a3 = *(const uint32_t*)&Qs[i1][ks * 16 + 2 * tig + 8];
#pragma unroll
        for (int nt = 0; nt < 7; nt++) {
            int n = nt * 8 + g;
            uint32_t b0 = *(const uint32_t*)&Ks[n][ks * 16 + 2 * tig];
            uint32_t b1 = *(const uint32_t*)&Ks[n][ks * 16 + 2 * tig + 8];
            mma16816(sc[nt], a0, a1, a2, a3, b0, b1);
        }
    }

    // --- combined bias+mask add (branch-free, padding baked in) ---
#pragma unroll
    for (int nt = 0; nt < 7; nt++) {
        int jc = nt * 8 + 2 * tig;
        float2 b0 = *(const float2*)&bm[i0 * 56 + jc];
        float2 b1 = *(const float2*)&bm[i1 * 56 + jc];
        sc[nt][0] += b0.x; sc[nt][1] += b0.y;
        sc[nt][2] += b1.x; sc[nt][3] += b1.y;
    }

    // --- softmax ---
    float mx0 = -1e30f, mx1 = -1e30f;
#pragma unroll
    for (int nt = 0; nt < 7; nt++) {
        mx0 = fmaxf(mx0, fmaxf(sc[nt][0], sc[nt][1]));
        mx1 = fmaxf(mx1, fmaxf(sc[nt][2], sc[nt][3]));
    }
    mx0 = fmaxf(mx0, __shfl_xor_sync(0xffffffffu, mx0, 1));
    mx0 = fmaxf(mx0, __shfl_xor_sync(0xffffffffu, mx0, 2));
    mx1 = fmaxf(mx1, __shfl_xor_sync(0xffffffffu, mx1, 1));
    mx1 = fmaxf(mx1, __shfl_xor_sync(0xffffffffu, mx1, 2));

    float s0 = 0.f, s1 = 0.f;
#pragma unroll
    for (int nt = 0; nt < 7; nt++) {
        sc[nt][0] = __expf(sc[nt][0] - mx0); s0 += sc[nt][0];
        sc[nt][1] = __expf(sc[nt][1] - mx0); s0 += sc[nt][1];
        sc[nt][2] = __expf(sc[nt][2] - mx1); s1 += sc[nt][2];
        sc[nt][3] = __expf(sc[nt][3] - mx1); s1 += sc[nt][3];
    }
    s0 += __shfl_xor_sync(0xffffffffu, s0, 1);
    s0 += __shfl_xor_sync(0xffffffffu, s0, 2);
    s1 += __shfl_xor_sync(0xffffffffu, s1, 1);
    s1 += __shfl_xor_sync(0xffffffffu, s1, 2);
    const float r0 = 1.f / s0, r1 = 1.f / s1;

    // stage P to smem (half)
#pragma unroll
    for (int nt = 0; nt < 7; nt++) {
        *(__half2*)&Ps[i0][nt * 8 + 2 * tig] = __floats2half2_rn(sc[nt][0], sc[nt][1]);
        *(__half2*)&Ps[i1][nt * 8 + 2 * tig] = __floats2half2_rn(sc[nt][2], sc[nt][3]);
    }
    __syncwarp();

    // --- ctx = P @ V ---
    float o[4][4];
#pragma unroll
    for (int nt = 0; nt < 4; nt++)
#pragma unroll
        for (int e = 0; e < 4; e++) o[nt][e] = 0.f;

#pragma unroll
    for (int kt = 0; kt < 4; kt++) {
        uint32_t a0 = *(const uint32_t*)&Ps[i0][kt * 16 + 2 * tig];
        uint32_t a1 = *(const uint32_t*)&Ps[i1][kt * 16 + 2 * tig];
        uint32_t a2 = *(const uint32_t*)&Ps[i0][kt * 16 + 2 * tig + 8];
        uint32_t a3 = *(const uint32_t*)&Ps[i1][kt * 16 + 2 * tig + 8];
#pragma unroll
        for (int nt = 0; nt < 4; nt++) {
            int n = nt * 8 + g;
            uint32_t b0 = *(const uint32_t*)&VsT[n][kt * 16 + 2 * tig];
            uint32_t b1 = *(const uint32_t*)&VsT[n][kt * 16 + 2 * tig + 8];
            mma16816(o[nt], a0, a1, a2, a3, b0, b1);
        }
    }

#pragma unroll
    for (int nt = 0; nt < 4; nt++) {
        int d = nt * 8 + 2 * tig;
        if (i0 < NTOK) {
            float2 v = make_float2(o[nt][0] * r0, o[nt][1] * r0);
            *(float2*)(out + ((size_t)b * NTOK + i0) * DMODEL + h * HDIM + d) = v;
        }
        if (i1 < NTOK) {
            float2 v = make_float2(o[nt][2] * r1, o[nt][3] * r1);
            *(float2*)(out + ((size_t)b * NTOK + i1) * DMODEL + h * HDIM + d) = v;
        }
    }
}

extern "C" void kernel_launch(void* const* d_in, const int* in_sizes, int n_in,
                              void* d_out, int out_size)
{
    (void)in_sizes; (void)n_in; (void)out_size;
    const float* hidden = (const float*)d_in[0];
    const float* amask  = (const float*)d_in[1];
    const float* wq     = (const float*)d_in[2];
    const float* bq     = (const float*)d_in[3];
    const float* wk     = (const float*)d_in[4];
    const float* bk     = (const float*)d_in[5];
    const float* wv     = (const float*)d_in[6];
    const float* bv     = (const float*)d_in[7];
    const float* table  = (const float*)d_in[8];
    float* out = (float*)d_out;

    cudaFuncSetAttribute(qkv_kernel, cudaFuncAttributeMaxDynamicSharedMemorySize,
                         2 * 128 * 264 * 2);

    convert_x<<<50176, 256>>>(hidden);
    convert_w<<<dim3(3, 256), 256>>>(wq, wk, wv);
    combine_bm<<<dim3(NWIN, NHD), 256>>>(amask, table);
    qkv_kernel<<<dim3(6, 1568), 256, 2 * 128 * 264 * 2>>>(bq, bk, bv);
    attn_kernel<<<dim3(NBATCH, NHD), 128>>>(out);
}

// round 4
// speedup vs baseline: 3.1293x; 1.4256x over previous
#include <cuda_runtime.h>
#include <cuda_fp16.h>
#include <cstdint>

#define NTOK   49
#define NHD    8
#define HDIM   32
#define DMODEL 256
#define NBATCH 4096
#define NWIN   64
#define MROWS  (NBATCH * NTOK)   // 200704

// fp16 scratch. +2048 halves padding: attn loads 64 padded rows per (b,h),
// overreading up to ~1KB past the last head; pad is zero-init (finite).
__device__ __half g_q[(size_t)NBATCH * NHD * NTOK * HDIM + 2048];
__device__ __half g_k[(size_t)NBATCH * NHD * NTOK * HDIM + 2048];
__device__ __half g_v[(size_t)NBATCH * NHD * NTOK * HDIM + 2048];
__device__ __half g_x[(size_t)MROWS * DMODEL];
__device__ __half g_w[3 * 256 * 256];           // [mat][n][k] (W transposed)
__device__ float  g_bm[NWIN * NHD * 64 * 64];   // combined mask+bias, padded

__device__ __forceinline__ void mma16816(float c[4],
                                         uint32_t a0, uint32_t a1, uint32_t a2, uint32_t a3,
                                         uint32_t b0, uint32_t b1) {
    asm volatile(
        "mma.sync.aligned.m16n8k16.row.col.f32.f16.f16.f32 "
        "{%0,%1,%2,%3}, {%4,%5,%6,%7}, {%8,%9}, {%0,%1,%2,%3};"
        : "+f"(c[0]), "+f"(c[1]), "+f"(c[2]), "+f"(c[3])
        : "r"(a0), "r"(a1), "r"(a2), "r"(a3), "r"(b0), "r"(b1));
}

__device__ __forceinline__ void ldsm4(uint32_t r[4], const void* p) {
    uint32_t a = (uint32_t)__cvta_generic_to_shared(p);
    asm volatile("ldmatrix.sync.aligned.m8n8.x4.shared.b16 {%0,%1,%2,%3}, [%4];"
                 : "=r"(r[0]), "=r"(r[1]), "=r"(r[2]), "=r"(r[3]) : "r"(a));
}

__device__ __forceinline__ void ldsm4t(uint32_t r[4], const void* p) {
    uint32_t a = (uint32_t)__cvta_generic_to_shared(p);
    asm volatile("ldmatrix.sync.aligned.m8n8.x4.trans.shared.b16 {%0,%1,%2,%3}, [%4];"
                 : "=r"(r[0]), "=r"(r[1]), "=r"(r[2]), "=r"(r[3]) : "r"(a));
}

__device__ __forceinline__ void cp16(void* s, const void* g) {
    uint32_t sa = (uint32_t)__cvta_generic_to_shared(s);
    asm volatile("cp.async.cg.shared.global [%0], [%1], 16;" :: "r"(sa), "l"(g));
}

// ---------------------------------------------------------------------------
__global__ __launch_bounds__(256) void convert_x(const float* __restrict__ X) {
    size_t t = (size_t)blockIdx.x * 256 + threadIdx.x;
    float4 v = ((const float4*)X)[t];
    __half2* o = (__half2*)(g_x + t * 4);
    o[0] = __floats2half2_rn(v.x, v.y);
    o[1] = __floats2half2_rn(v.z, v.w);
}

__global__ __launch_bounds__(256) void convert_w(const float* __restrict__ wq,
                                                 const float* __restrict__ wk,
                                                 const float* __restrict__ wv) {
    int mat = blockIdx.x, k = blockIdx.y, n = threadIdx.x;
    const float* W = (mat == 0) ? wq : (mat == 1) ? wk : wv;
    g_w[((size_t)mat * 256 + n) * 256 + k] = __float2half_rn(W[k * 256 + n]);
}

// Combined bias+mask: g_bm[w][h][i<64][j<64].
//   j>=49          : -1e30 (key padding; exp -> 0)
//   i>=49 (j<49)   : 0     (query pad rows; values discarded)
//   else           : mask[w][i][j] + table[relidx(i,j)][h]
__global__ __launch_bounds__(256) void combine_bm(const float* __restrict__ mask,
                                                  const float* __restrict__ table) {
    const int w = blockIdx.x, h = blockIdx.y;
    float* dst = g_bm + ((size_t)(w * NHD + h)) * 64 * 64;
    for (int idx = threadIdx.x; idx < 64 * 64; idx += 256) {
        int i = idx >> 6, j = idx & 63;
        float v;
        if (j >= NTOK)      v = -1e30f;
        else if (i >= NTOK) v = 0.f;
        else {
            int ih = i / 7, iw = i - ih * 7;
            int jh = j / 7, jw = j - jh * 7;
            int r = (ih - jh + 6) * 13 + (iw - jw + 6);
            v = mask[((size_t)w * NTOK + i) * NTOK + j] + table[r * NHD + h];
        }
        dst[idx] = v;
    }
}

// ---------------------------------------------------------------------------
// Kernel A: QKV projection. BM=128, BN=128, BK=64, 2-stage cp.async pipeline.
// 72KB smem -> 2 CTAs/SM (16 warps). 256 thr = 8 warps (2m x 4n), warp 64x32.
// ---------------------------------------------------------------------------
#define QKV_SMEM 73728    // 2 stages * (As 128x72 + Bs 128x72) halves * 2B

__global__ __launch_bounds__(256, 2) void qkv_kernel(
    const float* __restrict__ bq, const float* __restrict__ bk,
    const float* __restrict__ bv)
{
    extern __shared__ __half sm[];   // stage s: As at s*18432, Bs at +9216 (halves)

    const int bx = blockIdx.x, by = blockIdx.y;
    const int tid = threadIdx.x;
    const int warp = tid >> 5, lane = tid & 31;
    const int wm = warp & 1, wn = warp >> 1;
    const int g = lane >> 2, tig = lane & 3;

    const int mat   = bx >> 1;
    const int ncol0 = (bx & 1) * 128;
    const float* bias = (mat == 0) ? bq : (mat == 1) ? bk : bv;

    const __half* xrow  = g_x + (size_t)by * 128 * 256;
    const __half* wbase = g_w + ((size_t)mat * 256 + ncol0) * 256;

    auto loadStage = [&](int s, int kp) {
        __half* A = sm + s * 18432;
        __half* B = sm + s * 18432 + 9216;
        const __half* xs = xrow + kp * 64;
        const __half* ws = wbase + kp * 64;
#pragma unroll
        for (int c = tid; c < 1024; c += 256) {
            int r = c >> 3, off = (c & 7) * 8;
            cp16(A + r * 72 + off, xs + (size_t)r * 256 + off);
        }
#pragma unroll
        for (int c = tid; c < 1024; c += 256) {
            int r = c >> 3, off = (c & 7) * 8;
            cp16(B + r * 72 + off, ws + (size_t)r * 256 + off);
        }
        asm volatile("cp.async.commit_group;" ::: "memory");
    };

    loadStage(0, 0);
    loadStage(1, 1);

    float acc[4][4][4];
#pragma unroll
    for (int mt = 0; mt < 4; mt++)
#pragma unroll
        for (int nt = 0; nt < 4; nt++)
#pragma unroll
            for (int e = 0; e < 4; e++) acc[mt][nt][e] = 0.f;

    const int aRow = wm * 64 + (lane & 15);
    const int aCol = (lane & 16) >> 1;
    const int bRow = wn * 32 + (lane & 7) + ((lane & 16) >> 1);
    const int bCol = lane & 8;

#pragma unroll
    for (int kp = 0; kp < 4; kp++) {
        if (kp < 3) asm volatile("cp.async.wait_group 1;" ::: "memory");
        else        asm volatile("cp.async.wait_group 0;" ::: "memory");
        __syncthreads();

        const __half* A = sm + (kp & 1) * 18432;
        const __half* B = sm + (kp & 1) * 18432 + 9216;

#pragma unroll
        for (int ks = 0; ks < 4; ks++) {
            const int kc = ks * 16;
            uint32_t bf0[4], bf1[4];
            ldsm4(bf0, B + bRow * 72 + kc + bCol);
            ldsm4(bf1, B + (bRow + 16) * 72 + kc + bCol);
#pragma unroll
            for (int mt = 0; mt < 4; mt++) {
                uint32_t a[4];
                ldsm4(a, A + (aRow + mt * 16) * 72 + kc + aCol);
                mma16816(acc[mt][0], a[0], a[1], a[2], a[3], bf0[0], bf0[1]);
                mma16816(acc[mt][1], a[0], a[1], a[2], a[3], bf0[2], bf0[3]);
                mma16816(acc[mt][2], a[0], a[1], a[2], a[3], bf1[0], bf1[1]);
                mma16816(acc[mt][3], a[0], a[1], a[2], a[3], bf1[2], bf1[3]);
            }
        }

        if (kp < 2) {
            __syncthreads();
            loadStage(kp & 1, kp + 2);
        }
    }

    __half* outp = (mat == 0) ? g_q : (mat == 1) ? g_k : g_v;
    const float scale = (mat == 0) ? 0.17677669529663687f : 1.0f;
#pragma unroll
    for (int mt = 0; mt < 4; mt++) {
#pragma unroll
        for (int hf = 0; hf < 2; hf++) {
            int m = by * 128 + wm * 64 + mt * 16 + g + hf * 8;
            int b = m / NTOK, n = m - b * NTOK;
#pragma unroll
            for (int nt = 0; nt < 4; nt++) {
                int c = ncol0 + wn * 32 + nt * 8 + 2 * tig;
                int h = c >> 5, d = c & 31;
                float v0 = (acc[mt][nt][hf * 2 + 0] + bias[c]) * scale;
                float v1 = (acc[mt][nt][hf * 2 + 1] + bias[c + 1]) * scale;
                *(__half2*)(outp + ((((size_t)b * NHD + h) * NTOK + n) * HDIM + d)) =
                    __floats2half2_rn(v0, v1);
            }
        }
    }
}

// ---------------------------------------------------------------------------
// Kernel B: windowed attention. One 128-thr CTA per (b, h); warp w owns rows
// [16w, 16w+16). cp.async tile loads (no branches), ldmatrix fragments,
// trans-ldmatrix for V (no explicit transpose), coalesced staged output.
// ---------------------------------------------------------------------------
__global__ __launch_bounds__(128, 6) void attn_kernel(float* __restrict__ out)
{
    __shared__ alignas(128) char smraw[24576];
    __half (*Qs)[40] = (__half(*)[40])(smraw);            // 64 x 40  [token][d]
    __half (*Ks)[40] = (__half(*)[40])(smraw + 5120);     // 64 x 40  [token][d]
    __half (*Vs)[40] = (__half(*)[40])(smraw + 10240);    // 64 x 40  [token][d]
    __half (*Ps)[72] = (__half(*)[72])(smraw + 15360);    // 64 x 72  [i][j]
    float* Os = (float*)smraw;   // aliases Qs+Ks after QK phase (post-sync)

    const int b = blockIdx.x;
    const int h = blockIdx.y;
    const int w = b & (NWIN - 1);

    const int tid = threadIdx.x;
    const int warp = tid >> 5, lane = tid & 31;
    const int g = lane >> 2, tig = lane & 3;
    const int m0 = warp * 16;

    const size_t base = ((size_t)b * NHD + h) * (NTOK * HDIM);
    const __half* qp = g_q + base;
    const __half* kp = g_k + base;
    const __half* vp = g_v + base;
    const float* bm = g_bm + ((size_t)(w * NHD + h)) * 64 * 64;

    // cp.async loads: 64 rows x 32 halves each (rows >=49 read padded garbage;
    // finite, masked downstream).
#pragma unroll
    for (int c = tid; c < 256; c += 128) {
        int r = c >> 2, off = (c & 3) * 8;
        cp16(&Qs[r][off], qp + r * 32 + off);
    }
#pragma unroll
    for (int c = tid; c < 256; c += 128) {
        int r = c >> 2, off = (c & 3) * 8;
        cp16(&Ks[r][off], kp + r * 32 + off);
    }
#pragma unroll
    for (int c = tid; c < 256; c += 128) {
        int r = c >> 2, off = (c & 3) * 8;
        cp16(&Vs[r][off], vp + r * 32 + off);
    }
    asm volatile("cp.async.commit_group;" ::: "memory");
    asm volatile("cp.async.wait_group 0;" ::: "memory");
    __syncthreads();

    // --- scores = Q @ K^T  (64x64, 8 n8-tiles) ---
    float sc[8][4];
#pragma unroll
    for (int nt = 0; nt < 8; nt++)
#pragma unroll
        for (int e = 0; e < 4; e++) sc[nt][e] = 0.f;

#pragma unroll
    for (int ks = 0; ks < 2; ks++) {
        const int kc = ks * 16;
        uint32_t a[4];
        ldsm4(a, &Qs[m0 + (lane & 15)][kc + ((lane & 16) >> 1)]);
#pragma unroll
        for (int t = 0; t < 4; t++) {
            uint32_t bk_[4];
            ldsm4(bk_, &Ks[t * 16 + (lane & 7) + ((lane & 16) >> 1)][kc + (lane & 8)]);
            mma16816(sc[2 * t],     a[0], a[1], a[2], a[3], bk_[0], bk_[1]);
            mma16816(sc[2 * t + 1], a[0], a[1], a[2], a[3], bk_[2], bk_[3]);
        }
    }

    // --- combined bias+mask add (branch-free) ---
    const int i0 = m0 + g, i1 = i0 + 8;
#pragma unroll
    for (int nt = 0; nt < 8; nt++) {
        int jc = nt * 8 + 2 * tig;
        float2 b0 = *(const float2*)&bm[i0 * 64 + jc];
        float2 b1 = *(const float2*)&bm[i1 * 64 + jc];
        sc[nt][0] += b0.x; sc[nt][1] += b0.y;
        sc[nt][2] += b1.x; sc[nt][3] += b1.y;
    }

    // --- softmax (rows i0, i1; reduce across 4 tig lanes) ---
    float mx0 = -1e30f, mx1 = -1e30f;
#pragma unroll
    for (int nt = 0; nt < 8; nt++) {
        mx0 = fmaxf(mx0, fmaxf(sc[nt][0], sc[nt][1]));
        mx1 = fmaxf(mx1, fmaxf(sc[nt][2], sc[nt][3]));
    }
    mx0 = fmaxf(mx0, __shfl_xor_sync(0xffffffffu, mx0, 1));
    mx0 = fmaxf(mx0, __shfl_xor_sync(0xffffffffu, mx0, 2));
    mx1 = fmaxf(mx1, __shfl_xor_sync(0xffffffffu, mx1, 1));
    mx1 = fmaxf(mx1, __shfl_xor_sync(0xffffffffu, mx1, 2));

    float s0 = 0.f, s1 = 0.f;
#pragma unroll
    for (int nt = 0; nt < 8; nt++) {
        sc[nt][0] = __expf(sc[nt][0] - mx0); s0 += sc[nt][0];
        sc[nt][1] = __expf(sc[nt][1] - mx0); s0 += sc[nt][1];
        sc[nt][2] = __expf(sc[nt][2] - mx1); s1 += sc[nt][2];
        sc[nt][3] = __expf(sc[nt][3] - mx1); s1 += sc[nt][3];
    }
    s0 += __shfl_xor_sync(0xffffffffu, s0, 1);
    s0 += __shfl_xor_sync(0xffffffffu, s0, 2);
    s1 += __shfl_xor_sync(0xffffffffu, s1, 1);
    s1 += __shfl_xor_sync(0xffffffffu, s1, 2);
    const float r0 = 1.f / s0, r1 = 1.f / s1;

    // stage P (all 64 cols)
#pragma unroll
    for (int nt = 0; nt < 8; nt++) {
        int jc = nt * 8 + 2 * tig;
        *(__half2*)&Ps[i0][jc] = __floats2half2_rn(sc[nt][0], sc[nt][1]);
        *(__half2*)&Ps[i1][jc] = __floats2half2_rn(sc[nt][2], sc[nt][3]);
    }
    __syncwarp();

    // --- ctx = P @ V : A from Ps (ldsm), B from Vs via trans-ldsm ---
    float o[4][4];
#pragma unroll
    for (int nt = 0; nt < 4; nt++)
#pragma unroll
        for (int e = 0; e < 4; e++) o[nt][e] = 0.f;

#pragma unroll
    for (int kt = 0; kt < 4; kt++) {
        const int kc = kt * 16;
        uint32_t a[4];
        ldsm4(a, &Ps[m0 + (lane & 15)][kc + ((lane & 16) >> 1)]);
        uint32_t bv0[4], bv1[4];
        ldsm4t(bv0, &Vs[kc + (lane & 15)][0  + ((lane & 16) >> 1)]);
        ldsm4t(bv1, &Vs[kc + (lane & 15)][16 + ((lane & 16) >> 1)]);
        mma16816(o[0], a[0], a[1], a[2], a[3], bv0[0], bv0[1]);
        mma16816(o[1], a[0], a[1], a[2], a[3], bv0[2], bv0[3]);
        mma16816(o[2], a[0], a[1], a[2], a[3], bv1[0], bv1[1]);
        mma16816(o[3], a[0], a[1], a[2], a[3], bv1[2], bv1[3]);
    }

    // --- stage output to smem (aliases Qs/Ks), then coalesced float4 write ---
    __syncthreads();   // all Qs/Ks reads complete before Os overwrite
    float* Osw = Os + warp * 512;   // [16][32] per warp
#pragma unroll
    for (int nt = 0; nt < 4; nt++) {
        int d = nt * 8 + 2 * tig;
        *(float2*)&Osw[g * 32 + d]       = make_float2(o[nt][0] * r0, o[nt][1] * r0);
        *(float2*)&Osw[(g + 8) * 32 + d] = make_float2(o[nt][2] * r1, o[nt][3] * r1);
    }
    __syncwarp();
#pragma unroll
    for (int it = lane; it < 128; it += 32) {
        int r = it >> 3, c = (it & 7) * 4;
        int row = m0 + r;
        if (row < NTOK)
            *(float4*)(out + ((size_t)b * NTOK + row) * DMODEL + h * HDIM + c) =
                *(const float4*)&Osw[r * 32 + c];
    }
}

extern "C" void kernel_launch(void* const* d_in, const int* in_sizes, int n_in,
                              void* d_out, int out_size)
{
    (void)in_sizes; (void)n_in; (void)out_size;
    const float* hidden = (const float*)d_in[0];
    const float* amask  = (const float*)d_in[1];
    const float* wq     = (const float*)d_in[2];
    const float* bq     = (const float*)d_in[3];
    const float* wk     = (const float*)d_in[4];
    const float* bk     = (const float*)d_in[5];
    const float* wv     = (const float*)d_in[6];
    const float* bv     = (const float*)d_in[7];
    const float* table  = (const float*)d_in[8];
    float* out = (float*)d_out;

    cudaFuncSetAttribute(qkv_kernel, cudaFuncAttributeMaxDynamicSharedMemorySize,
                         QKV_SMEM);

    convert_x<<<50176, 256>>>(hidden);
    convert_w<<<dim3(3, 256), 256>>>(wq, wk, wv);
    combine_bm<<<dim3(NWIN, NHD), 256>>>(amask, table);
    qkv_kernel<<<dim3(6, 1568), 256, QKV_SMEM>>>(bq, bk, bv);
    attn_kernel<<<dim3(NBATCH, NHD), 128>>>(out);
}